// round 8
// baseline (speedup 1.0000x reference)
#include <cuda_runtime.h>
#include <cuda_fp16.h>
#include <cstdint>

#define NB 4
#define NN 2048
#define NF 128
#define RT 64        // rows per attention block (M)
#define KT 64        // j per K tile
#define NTILE (NN / KT)
#define SHIFT 4.0f

// ---- scratch (no cudaMalloc allowed) ----
__device__ __half g_WhT_h[NB * NF * NN];   // [b][o][n] fp16
__device__ float  g_f1[NB * NN];
__device__ float  g_f2[NB * NN];

// ---------------------------------------------------------------------------
__device__ __forceinline__ uint32_t smem_u32(const void* p) {
    uint32_t a;
    asm("{ .reg .u64 t; cvta.to.shared.u64 t, %1; cvt.u32.u64 %0, t; }" : "=r"(a) : "l"(p));
    return a;
}
__device__ __forceinline__ uint32_t swz(uint32_t x) { return x ^ ((x >> 3) & 0x70); }

__device__ __forceinline__ uint32_t pkh(float a, float b) {   // fp16x2: lo<-a, hi<-b
    uint32_t r;
    asm("cvt.rn.f16x2.f32 %0, %1, %2;" : "=r"(r) : "f"(b), "f"(a));
    return r;
}
__device__ __forceinline__ void ldm4(uint32_t* r, uint32_t addr) {
    asm volatile("ldmatrix.sync.aligned.m8n8.x4.shared.b16 {%0,%1,%2,%3}, [%4];"
        : "=r"(r[0]), "=r"(r[1]), "=r"(r[2]), "=r"(r[3]) : "r"(addr));
}
__device__ __forceinline__ void mma16816(float* d, const uint32_t* a, const uint32_t* b) {
    asm volatile("mma.sync.aligned.m16n8k16.row.col.f32.f16.f16.f32 "
        "{%0,%1,%2,%3}, {%4,%5,%6,%7}, {%8,%9}, {%0,%1,%2,%3};"
        : "+f"(d[0]), "+f"(d[1]), "+f"(d[2]), "+f"(d[3])
        : "r"(a[0]), "r"(a[1]), "r"(a[2]), "r"(a[3]), "r"(b[0]), "r"(b[1]));
}
#define CPA(dst, src) asm volatile("cp.async.cg.shared.global [%0], [%1], 16;" :: "r"(dst), "l"(src) : "memory")
#define CPC()   asm volatile("cp.async.commit_group;" ::: "memory")
#define CPW(n)  asm volatile("cp.async.wait_group %0;" :: "n"(n) : "memory")

// ---------------------------------------------------------------------------
// Kernel 1: Wh = h@W (fp32) ; f1/f2 ; WhT (fp16, coalesced via smem transpose)
// ---------------------------------------------------------------------------
__global__ void k_gemm1(const float* __restrict__ h,
                        const float* __restrict__ W,
                        const float* __restrict__ a) {
    extern __shared__ float sm1[];
    float* hs = sm1;
    float* Ws = sm1 + 32 * 128;
    int tid = threadIdx.x;
    int m0 = blockIdx.x * 32;

    {
        const float4* src = reinterpret_cast<const float4*>(h + (size_t)m0 * NF);
        float4* dst = reinterpret_cast<float4*>(hs);
        #pragma unroll
        for (int it = 0; it < 4; it++) dst[tid + it * 256] = src[tid + it * 256];
    }
    {
        const float4* src = reinterpret_cast<const float4*>(W);
        float4* dst = reinterpret_cast<float4*>(Ws);
        #pragma unroll
        for (int it = 0; it < 16; it++) dst[tid + it * 256] = src[tid + it * 256];
    }
    __syncthreads();

    int ty = tid >> 5;
    int tx = tid & 31;
    float acc[4][4] = {};

    #pragma unroll 4
    for (int k = 0; k < 128; k++) {
        float4 bv = *reinterpret_cast<const float4*>(&Ws[k * 128 + tx * 4]);
        #pragma unroll
        for (int mi = 0; mi < 4; mi++) {
            float av = hs[(ty * 4 + mi) * 128 + k];
            acc[mi][0] += av * bv.x;
            acc[mi][1] += av * bv.y;
            acc[mi][2] += av * bv.z;
            acc[mi][3] += av * bv.w;
        }
    }

    float a1v[4], a2v[4];
    #pragma unroll
    for (int ni = 0; ni < 4; ni++) {
        a1v[ni] = a[tx * 4 + ni];
        a2v[ni] = a[NF + tx * 4 + ni];
    }
    #pragma unroll
    for (int mi = 0; mi < 4; mi++) {
        float p1 = acc[mi][0] * a1v[0] + acc[mi][1] * a1v[1]
                 + acc[mi][2] * a1v[2] + acc[mi][3] * a1v[3];
        float p2 = acc[mi][0] * a2v[0] + acc[mi][1] * a2v[1]
                 + acc[mi][2] * a2v[2] + acc[mi][3] * a2v[3];
        #pragma unroll
        for (int off = 16; off > 0; off >>= 1) {
            p1 += __shfl_xor_sync(0xffffffffu, p1, off);
            p2 += __shfl_xor_sync(0xffffffffu, p2, off);
        }
        if (tx == 0) {
            g_f1[m0 + ty * 4 + mi] = p1;
            g_f2[m0 + ty * 4 + mi] = p2;
        }
    }

    // ---- transposed fp16 store via smem (coalesced) ----
    __syncthreads();                 // hs no longer needed
    uint32_t* su = reinterpret_cast<uint32_t*>(sm1);   // [128 o][16+1 pad] words
    #pragma unroll
    for (int ni = 0; ni < 4; ni++) {
        int o = tx * 4 + ni;
        su[o * 17 + ty * 2]     = pkh(acc[0][ni], acc[1][ni]);
        su[o * 17 + ty * 2 + 1] = pkh(acc[2][ni], acc[3][ni]);
    }
    __syncthreads();
    int bb = m0 >> 11;
    int o = tid >> 1, half = tid & 1;
    uint32_t* dst = reinterpret_cast<uint32_t*>(g_WhT_h)
                    + (size_t)(bb * 128 + o) * 1024 + ((m0 & 2047) >> 1) + half * 8;
    const uint32_t* srcw = su + o * 17 + half * 8;
    #pragma unroll
    for (int i = 0; i < 8; i++) dst[i] = srcw[i];
}

// ---------------------------------------------------------------------------
// Kernel 2: fused masked-softmax attention + P@Wh via mma.sync (1-term fp16)
// ---------------------------------------------------------------------------
// smem byte offsets
#define AS_OFF  0u            // 2 bufs x 8KB (fp16 P tile)
#define BT_OFF  16384u        // 2 bufs x 16KB
#define ADJ_OFF 49152u        // 2 bufs x 16KB (64 rows x 64 ints)
#define F2_OFF  81920u        // 2048 floats
#define DI_OFF  90112u        // 64 floats
#define SMEM_TOT (90112 + 512)

// phase A for tile tt: P tile (fp16) into bufA[tt&1]; returns row-sum part
__device__ __forceinline__ float phase_a(int tt, char* smemA, float f1v, int r, int c8,
                                         const float* f2s, uint32_t aHiRel) {
    const int* adjs = reinterpret_cast<const int*>(smemA + ADJ_OFF + (uint32_t)(tt & 1) * 16384u)
                      + r * 64 + c8;
    int4 m0 = *reinterpret_cast<const int4*>(adjs);
    int4 m1 = *reinterpret_cast<const int4*>(adjs + 4);
    const float4* fv4 = reinterpret_cast<const float4*>(f2s + tt * KT + c8);
    float4 fa = fv4[0], fb = fv4[1];
    float s0 = f1v + fa.x; s0 = s0 > 0.f ? s0 : 0.2f * s0;
    float s1 = f1v + fa.y; s1 = s1 > 0.f ? s1 : 0.2f * s1;
    float s2 = f1v + fa.z; s2 = s2 > 0.f ? s2 : 0.2f * s2;
    float s3 = f1v + fa.w; s3 = s3 > 0.f ? s3 : 0.2f * s3;
    float p0 = (m0.x > 0) ? __expf(s0 - SHIFT) : 0.0f;
    float p1 = (m0.y > 0) ? __expf(s1 - SHIFT) : 0.0f;
    float p2 = (m0.z > 0) ? __expf(s2 - SHIFT) : 0.0f;
    float p3 = (m0.w > 0) ? __expf(s3 - SHIFT) : 0.0f;
    float s4 = f1v + fb.x; s4 = s4 > 0.f ? s4 : 0.2f * s4;
    float s5 = f1v + fb.y; s5 = s5 > 0.f ? s5 : 0.2f * s5;
    float s6 = f1v + fb.z; s6 = s6 > 0.f ? s6 : 0.2f * s6;
    float s7 = f1v + fb.w; s7 = s7 > 0.f ? s7 : 0.2f * s7;
    float p4 = (m1.x > 0) ? __expf(s4 - SHIFT) : 0.0f;
    float p5 = (m1.y > 0) ? __expf(s5 - SHIFT) : 0.0f;
    float p6 = (m1.z > 0) ? __expf(s6 - SHIFT) : 0.0f;
    float p7 = (m1.w > 0) ? __expf(s7 - SHIFT) : 0.0f;
    uint32_t off = AS_OFF + (uint32_t)(tt & 1) * 8192u + aHiRel;
    *reinterpret_cast<uint4*>(smemA + off) =
        make_uint4(pkh(p0, p1), pkh(p2, p3), pkh(p4, p5), pkh(p6, p7));
    return ((p0 + p1) + (p2 + p3)) + ((p4 + p5) + (p6 + p7));
}

__global__ void __launch_bounds__(512, 1)
k_attn(const int* __restrict__ adj, float* __restrict__ out) {
    extern __shared__ char smemA[];
    uint32_t sb = smem_u32(smemA);
    int tid = threadIdx.x;
    int wid = tid >> 5;
    int lane = tid & 31;
    int b = blockIdx.y;
    int row0 = blockIdx.x * RT;

    float* f2s = reinterpret_cast<float*>(smemA + F2_OFF);
    float* di = reinterpret_cast<float*>(smemA + DI_OFF);

    // ---- preload f2 row (8KB) ----
    {
        const float4* s4 = reinterpret_cast<const float4*>(g_f2 + b * NN);
        reinterpret_cast<float4*>(f2s)[tid] = s4[tid];
    }

    // ---- per-thread phase-A constants ----
    int r = tid >> 3;
    int c8 = (tid & 7) * 8;
    float f1v = g_f1[b * NN + row0 + r];
    uint32_t aHiRel = swz((uint32_t)(r * 128 + (tid & 7) * 16));

    // ---- MMA fragment addresses ----
    int wr = wid >> 2, wc = wid & 3;
    uint32_t aRowOff = (uint32_t)((wr * 16 + (lane & 7) + ((lane >> 3) & 1) * 8) * 128
                                  + (((lane >> 4) & 1) * 8) * 2);
    int bRow = wc * 32 + ((lane >> 4) & 1) * 8 + (lane & 7);
    uint32_t bColOff = (uint32_t)(((lane >> 3) & 1) * 16);
    uint32_t bBase = (uint32_t)(bRow * 128) + bColOff;

    // cp.async B mapping (2 x 16B per thread per tile)
    uint32_t cpDst[2];
    const __half* cpSrcBase[2];
    #pragma unroll
    for (int k = 0; k < 2; k++) {
        int s = tid + k * 512;
        int o = s >> 3, seg = s & 7;
        cpDst[k] = swz((uint32_t)(o * 128 + seg * 16));
        cpSrcBase[k] = g_WhT_h + ((size_t)(b * 128 + o) * NN + seg * 8);
    }
    // cp.async adj mapping (2 x 16B per thread per tile)
    const int* aSrc0 = adj + (size_t)(row0 + (tid >> 4)) * NN + (tid & 15) * 4;
    const int* aSrc1 = aSrc0 + (size_t)32 * NN;
    uint32_t aDst0 = (uint32_t)tid * 16u;
    uint32_t aDst1 = aDst0 + 8192u;

    float acc[4][4] = {};
    float dacc = 0.0f;

    // prologue: B(0) + adj(0) + adj(1) in one group
    {
        uint32_t dbase = sb + BT_OFF;
        CPA(dbase + cpDst[0], cpSrcBase[0]);
        CPA(dbase + cpDst[1], cpSrcBase[1]);
        uint32_t ad0 = sb + ADJ_OFF;
        CPA(ad0 + aDst0, aSrc0);
        CPA(ad0 + aDst1, aSrc1);
        uint32_t ad1 = sb + ADJ_OFF + 16384u;
        CPA(ad1 + aDst0, aSrc0 + KT);
        CPA(ad1 + aDst1, aSrc1 + KT);
        CPC();
    }
    CPW(0);
    __syncthreads();
    dacc += phase_a(0, smemA, f1v, r, c8, f2s, aHiRel);

    for (int t = 0; t < NTILE; t++) {
        uint32_t bufB = sb + BT_OFF + (uint32_t)(t & 1) * 16384u;

        __syncthreads();   // phaseA(t) + MMA(t-1) complete everywhere

        if (t + 1 < NTILE) {
            uint32_t dbase = sb + BT_OFF + (uint32_t)((t + 1) & 1) * 16384u;
            CPA(dbase + cpDst[0], cpSrcBase[0] + (t + 1) * KT);
            CPA(dbase + cpDst[1], cpSrcBase[1] + (t + 1) * KT);
            if (t + 2 < NTILE) {
                uint32_t adb = sb + ADJ_OFF + (uint32_t)(t & 1) * 16384u;
                CPA(adb + aDst0, aSrc0 + (t + 2) * KT);
                CPA(adb + aDst1, aSrc1 + (t + 2) * KT);
            }
            CPC();
            CPW(1);        // {B(t), adj(t+1)} landed
            dacc += phase_a(t + 1, smemA, f1v, r, c8, f2s, aHiRel);
        } else {
            CPW(0);
        }

        // ---- MMA(t): 4 ksteps x 4 nfrags ----
        uint32_t bufA = sb + AS_OFF + (uint32_t)(t & 1) * 8192u;
        #pragma unroll
        for (int ks = 0; ks < 4; ks++) {
            uint32_t ah[4], bh[8];
            ldm4(ah, bufA + swz(aRowOff + 32u * ks));
            ldm4(bh + 0, bufB + swz(bBase + 32u * ks));
            ldm4(bh + 4, bufB + swz(bBase + 2048u + 32u * ks));
            #pragma unroll
            for (int nb = 0; nb < 4; nb++) mma16816(acc[nb], ah, bh + nb * 2);
        }
    }

    // ---- softmax denominator ----
    dacc += __shfl_xor_sync(0xffffffffu, dacc, 1);
    dacc += __shfl_xor_sync(0xffffffffu, dacc, 2);
    dacc += __shfl_xor_sync(0xffffffffu, dacc, 4);
    if ((lane & 7) == 0) di[wid * 4 + (lane >> 3)] = 1.0f / dacc;
    __syncthreads();

    // ---- epilogue: scale + store ----
    int rA = wr * 16 + (lane >> 2);
    float d0 = di[rA];
    float d1 = di[rA + 8];
    float* orow0 = out + ((size_t)(b * NN + row0 + rA)) * NF + wc * 32 + 2 * (lane & 3);
    float* orow1 = orow0 + 8 * NF;
    #pragma unroll
    for (int nb = 0; nb < 4; nb++) {
        *reinterpret_cast<float2*>(orow0 + nb * 8) =
            make_float2(acc[nb][0] * d0, acc[nb][1] * d0);
        *reinterpret_cast<float2*>(orow1 + nb * 8) =
            make_float2(acc[nb][2] * d1, acc[nb][3] * d1);
    }
}

// ---------------------------------------------------------------------------
extern "C" void kernel_launch(void* const* d_in, const int* in_sizes, int n_in,
                              void* d_out, int out_size) {
    const float* h   = (const float*)d_in[0];
    const int*   adj = (const int*)d_in[1];
    const float* W   = (const float*)d_in[2];
    const float* a   = (const float*)d_in[3];
    float* out = (float*)d_out;

    int sm1 = (32 * 128 + 128 * 128) * 4;
    cudaFuncSetAttribute(k_gemm1, cudaFuncAttributeMaxDynamicSharedMemorySize, sm1);
    cudaFuncSetAttribute(k_attn,  cudaFuncAttributeMaxDynamicSharedMemorySize, SMEM_TOT);

    k_gemm1<<<(NB * NN) / 32, 256, sm1>>>(h, W, a);
    k_attn<<<dim3(NN / RT, NB), 512, SMEM_TOT>>>(adj, out);
}

// round 9
// speedup vs baseline: 1.1925x; 1.1925x over previous
#include <cuda_runtime.h>
#include <cuda_fp16.h>
#include <cstdint>

#define NB 4
#define NN 2048
#define NF 128
#define RT 64        // rows per attention block (M)
#define KT 64        // j per K tile
#define NTILE (NN / KT)
#define SHIFT 4.0f

// ---- scratch (no cudaMalloc allowed) ----
__device__ __half g_WhT_h[NB * NF * NN];   // [b][o][n] fp16 hi
__device__ __half g_WhT_l[NB * NF * NN];   // [b][o][n] fp16 lo
__device__ float  g_f1[NB * NN];
__device__ float  g_f2[NB * NN];

// ---------------------------------------------------------------------------
__device__ __forceinline__ uint32_t smem_u32(const void* p) {
    uint32_t a;
    asm("{ .reg .u64 t; cvta.to.shared.u64 t, %1; cvt.u32.u64 %0, t; }" : "=r"(a) : "l"(p));
    return a;
}
__device__ __forceinline__ uint32_t swz(uint32_t x) { return x ^ ((x >> 3) & 0x70); }

__device__ __forceinline__ uint32_t pkh(float a, float b) {   // fp16x2: lo<-a, hi<-b
    uint32_t r;
    asm("cvt.rn.f16x2.f32 %0, %1, %2;" : "=r"(r) : "f"(b), "f"(a));
    return r;
}
__device__ __forceinline__ void ldm4(uint32_t* r, uint32_t addr) {
    asm volatile("ldmatrix.sync.aligned.m8n8.x4.shared.b16 {%0,%1,%2,%3}, [%4];"
        : "=r"(r[0]), "=r"(r[1]), "=r"(r[2]), "=r"(r[3]) : "r"(addr));
}
__device__ __forceinline__ void mma16816(float* d, const uint32_t* a, const uint32_t* b) {
    asm volatile("mma.sync.aligned.m16n8k16.row.col.f32.f16.f16.f32 "
        "{%0,%1,%2,%3}, {%4,%5,%6,%7}, {%8,%9}, {%0,%1,%2,%3};"
        : "+f"(d[0]), "+f"(d[1]), "+f"(d[2]), "+f"(d[3])
        : "r"(a[0]), "r"(a[1]), "r"(a[2]), "r"(a[3]), "r"(b[0]), "r"(b[1]));
}
#define CPA(dst, src) asm volatile("cp.async.cg.shared.global [%0], [%1], 16;" :: "r"(dst), "l"(src) : "memory")
#define CPC()   asm volatile("cp.async.commit_group;" ::: "memory")
#define CPW(n)  asm volatile("cp.async.wait_group %0;" :: "n"(n) : "memory")

// ---------------------------------------------------------------------------
// Kernel 1: Wh = h@W (fp32) ; f1/f2 ; WhT hi/lo (fp16, coalesced stores)
// ---------------------------------------------------------------------------
__global__ void k_gemm1(const float* __restrict__ h,
                        const float* __restrict__ W,
                        const float* __restrict__ a) {
    extern __shared__ float sm1[];
    float* hs = sm1;
    float* Ws = sm1 + 32 * 128;
    int tid = threadIdx.x;
    int m0 = blockIdx.x * 32;

    {
        const float4* src = reinterpret_cast<const float4*>(h + (size_t)m0 * NF);
        float4* dst = reinterpret_cast<float4*>(hs);
        #pragma unroll
        for (int it = 0; it < 4; it++) dst[tid + it * 256] = src[tid + it * 256];
    }
    {
        const float4* src = reinterpret_cast<const float4*>(W);
        float4* dst = reinterpret_cast<float4*>(Ws);
        #pragma unroll
        for (int it = 0; it < 16; it++) dst[tid + it * 256] = src[tid + it * 256];
    }
    __syncthreads();

    int ty = tid >> 5;
    int tx = tid & 31;
    float acc[4][4] = {};

    #pragma unroll 4
    for (int k = 0; k < 128; k++) {
        float4 bv = *reinterpret_cast<const float4*>(&Ws[k * 128 + tx * 4]);
        #pragma unroll
        for (int mi = 0; mi < 4; mi++) {
            float av = hs[(ty * 4 + mi) * 128 + k];
            acc[mi][0] += av * bv.x;
            acc[mi][1] += av * bv.y;
            acc[mi][2] += av * bv.z;
            acc[mi][3] += av * bv.w;
        }
    }

    float a1v[4], a2v[4];
    #pragma unroll
    for (int ni = 0; ni < 4; ni++) {
        a1v[ni] = a[tx * 4 + ni];
        a2v[ni] = a[NF + tx * 4 + ni];
    }
    #pragma unroll
    for (int mi = 0; mi < 4; mi++) {
        float p1 = acc[mi][0] * a1v[0] + acc[mi][1] * a1v[1]
                 + acc[mi][2] * a1v[2] + acc[mi][3] * a1v[3];
        float p2 = acc[mi][0] * a2v[0] + acc[mi][1] * a2v[1]
                 + acc[mi][2] * a2v[2] + acc[mi][3] * a2v[3];
        #pragma unroll
        for (int off = 16; off > 0; off >>= 1) {
            p1 += __shfl_xor_sync(0xffffffffu, p1, off);
            p2 += __shfl_xor_sync(0xffffffffu, p2, off);
        }
        if (tx == 0) {
            g_f1[m0 + ty * 4 + mi] = p1;
            g_f2[m0 + ty * 4 + mi] = p2;
        }
    }

    // ---- transposed fp16 hi/lo store via smem (coalesced) ----
    __syncthreads();                 // hs/Ws no longer needed
    uint32_t* su = reinterpret_cast<uint32_t*>(sm1);            // hi [128][17]
    uint32_t* sl = su + 128 * 17;                               // lo [128][17]
    #pragma unroll
    for (int ni = 0; ni < 4; ni++) {
        int o = tx * 4 + ni;
        float v0 = acc[0][ni], v1 = acc[1][ni], v2 = acc[2][ni], v3 = acc[3][ni];
        uint32_t hA = pkh(v0, v1);
        uint32_t hB = pkh(v2, v3);
        float2 fA = __half22float2(*reinterpret_cast<__half2*>(&hA));
        float2 fB = __half22float2(*reinterpret_cast<__half2*>(&hB));
        su[o * 17 + ty * 2]     = hA;
        su[o * 17 + ty * 2 + 1] = hB;
        sl[o * 17 + ty * 2]     = pkh(v0 - fA.x, v1 - fA.y);
        sl[o * 17 + ty * 2 + 1] = pkh(v2 - fB.x, v3 - fB.y);
    }
    __syncthreads();
    int bb = m0 >> 11;
    int o = tid >> 1, half = tid & 1;
    size_t gbase = (size_t)(bb * 128 + o) * 1024 + ((m0 & 2047) >> 1) + half * 8;
    uint32_t* dh = reinterpret_cast<uint32_t*>(g_WhT_h) + gbase;
    uint32_t* dl = reinterpret_cast<uint32_t*>(g_WhT_l) + gbase;
    const uint32_t* sh = su + o * 17 + half * 8;
    const uint32_t* slo = sl + o * 17 + half * 8;
    uint4 t0 = make_uint4(sh[0], sh[1], sh[2], sh[3]);
    uint4 t1 = make_uint4(sh[4], sh[5], sh[6], sh[7]);
    uint4 t2 = make_uint4(slo[0], slo[1], slo[2], slo[3]);
    uint4 t3 = make_uint4(slo[4], slo[5], slo[6], slo[7]);
    *reinterpret_cast<uint4*>(dh)     = t0;
    *reinterpret_cast<uint4*>(dh + 4) = t1;
    *reinterpret_cast<uint4*>(dl)     = t2;
    *reinterpret_cast<uint4*>(dl + 4) = t3;
}

// ---------------------------------------------------------------------------
// Kernel 2: fused masked-softmax attention + P@Wh (2-term fp16, 1024 threads)
// ---------------------------------------------------------------------------
// smem byte offsets
#define AS_OFF  0u            // 2 bufs x 8KB (fp16 P tile)
#define BT_OFF  16384u        // 2 bufs x (hi 16KB + lo 16KB)
#define ADJ_OFF 81920u        // 2 bufs x 16KB (64 rows x 64 ints)
#define F2_OFF  114688u       // 2048 floats
#define DI_OFF  122880u       // 64 floats
#define SMEM_TOT (122880 + 512)

// phase A for tile tt: 4 j per thread; P (fp16) into bufA[tt&1]; row-sum part
__device__ __forceinline__ float phase_a(int tt, char* smemA, float f1v, int r, int c4,
                                         const float* f2s, uint32_t aRel) {
    const int* adjs = reinterpret_cast<const int*>(smemA + ADJ_OFF + (uint32_t)(tt & 1) * 16384u)
                      + r * 64 + c4;
    int4 m0 = *reinterpret_cast<const int4*>(adjs);
    float4 fa = *reinterpret_cast<const float4*>(f2s + tt * KT + c4);
    float s0 = f1v + fa.x; s0 = s0 > 0.f ? s0 : 0.2f * s0;
    float s1 = f1v + fa.y; s1 = s1 > 0.f ? s1 : 0.2f * s1;
    float s2 = f1v + fa.z; s2 = s2 > 0.f ? s2 : 0.2f * s2;
    float s3 = f1v + fa.w; s3 = s3 > 0.f ? s3 : 0.2f * s3;
    float p0 = (m0.x > 0) ? __expf(s0 - SHIFT) : 0.0f;
    float p1 = (m0.y > 0) ? __expf(s1 - SHIFT) : 0.0f;
    float p2 = (m0.z > 0) ? __expf(s2 - SHIFT) : 0.0f;
    float p3 = (m0.w > 0) ? __expf(s3 - SHIFT) : 0.0f;
    uint32_t off = AS_OFF + (uint32_t)(tt & 1) * 8192u + aRel;
    *reinterpret_cast<uint2*>(smemA + off) = make_uint2(pkh(p0, p1), pkh(p2, p3));
    return (p0 + p1) + (p2 + p3);
}

__global__ void __launch_bounds__(1024, 1)
k_attn(const int* __restrict__ adj, float* __restrict__ out) {
    extern __shared__ char smemA[];
    uint32_t sb = smem_u32(smemA);
    int tid = threadIdx.x;
    int wid = tid >> 5;
    int lane = tid & 31;
    int b = blockIdx.y;
    int row0 = blockIdx.x * RT;

    float* f2s = reinterpret_cast<float*>(smemA + F2_OFF);
    float* di = reinterpret_cast<float*>(smemA + DI_OFF);

    // ---- preload f2 row (8KB) ----
    {
        const float2* s2 = reinterpret_cast<const float2*>(g_f2 + b * NN);
        reinterpret_cast<float2*>(f2s)[tid] = s2[tid];
    }

    // ---- per-thread phase-A constants ----
    int r = tid >> 4;                 // 0..63
    int c4 = (tid & 15) * 4;          // j offset within tile
    float f1v = g_f1[b * NN + row0 + r];
    uint32_t aRel = swz((uint32_t)(r * 128 + (tid & 15) * 8));

    // ---- MMA fragment addresses (warp: 16 rows x 16 cols) ----
    int wr = wid >> 3, wc = wid & 7;
    uint32_t aRowOff = (uint32_t)((wr * 16 + (lane & 7) + ((lane >> 3) & 1) * 8) * 128
                                  + ((lane >> 4) & 1) * 16);
    int bRow = wc * 16 + ((lane >> 4) & 1) * 8 + (lane & 7);
    uint32_t bBase = (uint32_t)(bRow * 128) + (uint32_t)(((lane >> 3) & 1) * 16);

    // cp.async B mapping (2 x 16B per thread per tile: hi + lo planes)
    uint32_t cpDst[2];
    const __half* cpSrcBase[2];
    #pragma unroll
    for (int k = 0; k < 2; k++) {
        int s = tid + k * 1024;
        int split = s >> 10, s2 = s & 1023;
        int o = s2 >> 3, seg = s2 & 7;
        cpDst[k] = (uint32_t)split * 16384u + swz((uint32_t)(o * 128 + seg * 16));
        cpSrcBase[k] = (split ? g_WhT_l : g_WhT_h) + ((size_t)(b * 128 + o) * NN + seg * 8);
    }
    // cp.async adj mapping (1 x 16B per thread per tile)
    const int* aSrc0 = adj + (size_t)(row0 + (tid >> 4)) * NN + (tid & 15) * 4;
    uint32_t aDst0 = (uint32_t)tid * 16u;

    float acch[2][4] = {};
    float accl[2][4] = {};
    float dacc = 0.0f;

    // prologue: B(0) + adj(0) + adj(1) in one group
    {
        uint32_t dbase = sb + BT_OFF;
        CPA(dbase + cpDst[0], cpSrcBase[0]);
        CPA(dbase + cpDst[1], cpSrcBase[1]);
        CPA(sb + ADJ_OFF + aDst0, aSrc0);
        CPA(sb + ADJ_OFF + 16384u + aDst0, aSrc0 + KT);
        CPC();
    }
    CPW(0);
    __syncthreads();
    dacc += phase_a(0, smemA, f1v, r, c4, f2s, aRel);

    for (int t = 0; t < NTILE; t++) {
        uint32_t bufB = sb + BT_OFF + (uint32_t)(t & 1) * 32768u;

        __syncthreads();   // phaseA(t) + MMA(t-1) complete everywhere

        if (t + 1 < NTILE) {
            uint32_t dbase = sb + BT_OFF + (uint32_t)((t + 1) & 1) * 32768u;
            CPA(dbase + cpDst[0], cpSrcBase[0] + (t + 1) * KT);
            CPA(dbase + cpDst[1], cpSrcBase[1] + (t + 1) * KT);
            if (t + 2 < NTILE) {
                uint32_t adb = sb + ADJ_OFF + (uint32_t)(t & 1) * 16384u;
                CPA(adb + aDst0, aSrc0 + (t + 2) * KT);
            }
            CPC();
            CPW(1);        // {B(t), adj(t+1)} landed
            dacc += phase_a(t + 1, smemA, f1v, r, c4, f2s, aRel);
        } else {
            CPW(0);
        }

        // ---- MMA(t): 4 ksteps x (2 terms x 2 nfrags) ----
        uint32_t bufA = sb + AS_OFF + (uint32_t)(t & 1) * 8192u;
        #pragma unroll
        for (int ks = 0; ks < 4; ks++) {
            uint32_t ah[4], bh[4], bl[4];
            ldm4(ah, bufA + swz(aRowOff + 32u * ks));
            uint32_t bAddr = swz(bBase + 32u * ks);
            ldm4(bh, bufB + bAddr);
            ldm4(bl, bufB + 16384u + bAddr);
            mma16816(acch[0], ah, bh + 0);
            mma16816(acch[1], ah, bh + 2);
            mma16816(accl[0], ah, bl + 0);
            mma16816(accl[1], ah, bl + 2);
        }
    }

    // ---- softmax denominator (16 threads per row) ----
    dacc += __shfl_xor_sync(0xffffffffu, dacc, 1);
    dacc += __shfl_xor_sync(0xffffffffu, dacc, 2);
    dacc += __shfl_xor_sync(0xffffffffu, dacc, 4);
    dacc += __shfl_xor_sync(0xffffffffu, dacc, 8);
    if ((lane & 15) == 0) di[r] = 1.0f / dacc;
    __syncthreads();

    // ---- epilogue: merge terms, scale, store ----
    int rA = wr * 16 + (lane >> 2);
    float d0 = di[rA];
    float d1 = di[rA + 8];
    float* orow0 = out + ((size_t)(b * NN + row0 + rA)) * NF + wc * 16 + 2 * (lane & 3);
    float* orow1 = orow0 + 8 * NF;
    #pragma unroll
    for (int nb = 0; nb < 2; nb++) {
        *reinterpret_cast<float2*>(orow0 + nb * 8) =
            make_float2((acch[nb][0] + accl[nb][0]) * d0, (acch[nb][1] + accl[nb][1]) * d0);
        *reinterpret_cast<float2*>(orow1 + nb * 8) =
            make_float2((acch[nb][2] + accl[nb][2]) * d1, (acch[nb][3] + accl[nb][3]) * d1);
    }
}

// ---------------------------------------------------------------------------
extern "C" void kernel_launch(void* const* d_in, const int* in_sizes, int n_in,
                              void* d_out, int out_size) {
    const float* h   = (const float*)d_in[0];
    const int*   adj = (const int*)d_in[1];
    const float* W   = (const float*)d_in[2];
    const float* a   = (const float*)d_in[3];
    float* out = (float*)d_out;

    int sm1 = (32 * 128 + 128 * 128) * 4;
    cudaFuncSetAttribute(k_gemm1, cudaFuncAttributeMaxDynamicSharedMemorySize, sm1);
    cudaFuncSetAttribute(k_attn,  cudaFuncAttributeMaxDynamicSharedMemorySize, SMEM_TOT);

    k_gemm1<<<(NB * NN) / 32, 256, sm1>>>(h, W, a);
    k_attn<<<dim3(NN / RT, NB), 1024, SMEM_TOT>>>(adj, out);
}

// round 10
// speedup vs baseline: 1.2385x; 1.0386x over previous
#include <cuda_runtime.h>
#include <cuda_fp16.h>
#include <cstdint>

#define NB 4
#define NN 2048
#define NF 128
#define RT 64        // rows per attention block (M)
#define KT 64        // j per K tile
#define NTILE (NN / KT)
#define SHIFT 4.0f

// ---- scratch (no cudaMalloc allowed) ----
__device__ __half g_WhT_h[NB * NF * NN];   // [b][o][n] fp16 hi
__device__ __half g_WhT_l[NB * NF * NN];   // [b][o][n] fp16 lo
__device__ float  g_f1[NB * NN];
__device__ float  g_f2[NB * NN];

// ---------------------------------------------------------------------------
__device__ __forceinline__ uint32_t smem_u32(const void* p) {
    uint32_t a;
    asm("{ .reg .u64 t; cvta.to.shared.u64 t, %1; cvt.u32.u64 %0, t; }" : "=r"(a) : "l"(p));
    return a;
}
__device__ __forceinline__ uint32_t swz(uint32_t x) { return x ^ ((x >> 3) & 0x70); }

__device__ __forceinline__ uint32_t pkh(float a, float b) {   // fp16x2: lo<-a, hi<-b
    uint32_t r;
    asm("cvt.rn.f16x2.f32 %0, %1, %2;" : "=r"(r) : "f"(b), "f"(a));
    return r;
}
__device__ __forceinline__ void ldm4(uint32_t* r, uint32_t addr) {
    asm volatile("ldmatrix.sync.aligned.m8n8.x4.shared.b16 {%0,%1,%2,%3}, [%4];"
        : "=r"(r[0]), "=r"(r[1]), "=r"(r[2]), "=r"(r[3]) : "r"(addr));
}
__device__ __forceinline__ void mma16816(float* d, const uint32_t* a, const uint32_t* b) {
    asm volatile("mma.sync.aligned.m16n8k16.row.col.f32.f16.f16.f32 "
        "{%0,%1,%2,%3}, {%4,%5,%6,%7}, {%8,%9}, {%0,%1,%2,%3};"
        : "+f"(d[0]), "+f"(d[1]), "+f"(d[2]), "+f"(d[3])
        : "r"(a[0]), "r"(a[1]), "r"(a[2]), "r"(a[3]), "r"(b[0]), "r"(b[1]));
}
#define CPA(dst, src) asm volatile("cp.async.cg.shared.global [%0], [%1], 16;" :: "r"(dst), "l"(src) : "memory")
#define CPC()   asm volatile("cp.async.commit_group;" ::: "memory")
#define CPW(n)  asm volatile("cp.async.wait_group %0;" :: "n"(n) : "memory")

// ---------------------------------------------------------------------------
// Kernel 1: Wh = h@W (fp32) ; f1/f2 ; WhT hi/lo (fp16, coalesced stores)
// ---------------------------------------------------------------------------
__global__ void k_gemm1(const float* __restrict__ h,
                        const float* __restrict__ W,
                        const float* __restrict__ a) {
    extern __shared__ float sm1[];
    float* hs = sm1;
    float* Ws = sm1 + 32 * 128;
    int tid = threadIdx.x;
    int m0 = blockIdx.x * 32;

    {
        const float4* src = reinterpret_cast<const float4*>(h + (size_t)m0 * NF);
        float4* dst = reinterpret_cast<float4*>(hs);
        #pragma unroll
        for (int it = 0; it < 4; it++) dst[tid + it * 256] = src[tid + it * 256];
    }
    {
        const float4* src = reinterpret_cast<const float4*>(W);
        float4* dst = reinterpret_cast<float4*>(Ws);
        #pragma unroll
        for (int it = 0; it < 16; it++) dst[tid + it * 256] = src[tid + it * 256];
    }
    __syncthreads();

    int ty = tid >> 5;
    int tx = tid & 31;
    float acc[4][4] = {};

    #pragma unroll 4
    for (int k = 0; k < 128; k++) {
        float4 bv = *reinterpret_cast<const float4*>(&Ws[k * 128 + tx * 4]);
        #pragma unroll
        for (int mi = 0; mi < 4; mi++) {
            float av = hs[(ty * 4 + mi) * 128 + k];
            acc[mi][0] += av * bv.x;
            acc[mi][1] += av * bv.y;
            acc[mi][2] += av * bv.z;
            acc[mi][3] += av * bv.w;
        }
    }

    float a1v[4], a2v[4];
    #pragma unroll
    for (int ni = 0; ni < 4; ni++) {
        a1v[ni] = a[tx * 4 + ni];
        a2v[ni] = a[NF + tx * 4 + ni];
    }
    #pragma unroll
    for (int mi = 0; mi < 4; mi++) {
        float p1 = acc[mi][0] * a1v[0] + acc[mi][1] * a1v[1]
                 + acc[mi][2] * a1v[2] + acc[mi][3] * a1v[3];
        float p2 = acc[mi][0] * a2v[0] + acc[mi][1] * a2v[1]
                 + acc[mi][2] * a2v[2] + acc[mi][3] * a2v[3];
        #pragma unroll
        for (int off = 16; off > 0; off >>= 1) {
            p1 += __shfl_xor_sync(0xffffffffu, p1, off);
            p2 += __shfl_xor_sync(0xffffffffu, p2, off);
        }
        if (tx == 0) {
            g_f1[m0 + ty * 4 + mi] = p1;
            g_f2[m0 + ty * 4 + mi] = p2;
        }
    }

    // ---- transposed fp16 hi/lo store via smem (coalesced) ----
    __syncthreads();                 // hs/Ws no longer needed
    uint32_t* su = reinterpret_cast<uint32_t*>(sm1);            // hi [128][17]
    uint32_t* sl = su + 128 * 17;                               // lo [128][17]
    #pragma unroll
    for (int ni = 0; ni < 4; ni++) {
        int o = tx * 4 + ni;
        float v0 = acc[0][ni], v1 = acc[1][ni], v2 = acc[2][ni], v3 = acc[3][ni];
        uint32_t hA = pkh(v0, v1);
        uint32_t hB = pkh(v2, v3);
        float2 fA = __half22float2(*reinterpret_cast<__half2*>(&hA));
        float2 fB = __half22float2(*reinterpret_cast<__half2*>(&hB));
        su[o * 17 + ty * 2]     = hA;
        su[o * 17 + ty * 2 + 1] = hB;
        sl[o * 17 + ty * 2]     = pkh(v0 - fA.x, v1 - fA.y);
        sl[o * 17 + ty * 2 + 1] = pkh(v2 - fB.x, v3 - fB.y);
    }
    __syncthreads();
    int bb = m0 >> 11;
    int o = tid >> 1, half = tid & 1;
    size_t gbase = (size_t)(bb * 128 + o) * 1024 + ((m0 & 2047) >> 1) + half * 8;
    uint32_t* dh = reinterpret_cast<uint32_t*>(g_WhT_h) + gbase;
    uint32_t* dl = reinterpret_cast<uint32_t*>(g_WhT_l) + gbase;
    const uint32_t* sh = su + o * 17 + half * 8;
    const uint32_t* slo = sl + o * 17 + half * 8;
    uint4 t0 = make_uint4(sh[0], sh[1], sh[2], sh[3]);
    uint4 t1 = make_uint4(sh[4], sh[5], sh[6], sh[7]);
    uint4 t2 = make_uint4(slo[0], slo[1], slo[2], slo[3]);
    uint4 t3 = make_uint4(slo[4], slo[5], slo[6], slo[7]);
    *reinterpret_cast<uint4*>(dh)     = t0;
    *reinterpret_cast<uint4*>(dh + 4) = t1;
    *reinterpret_cast<uint4*>(dl)     = t2;
    *reinterpret_cast<uint4*>(dl + 4) = t3;
}

// ---------------------------------------------------------------------------
// Kernel 2: fused attention, 512 threads, warp tile 32x16, adj via LDG->regs
// ---------------------------------------------------------------------------
// smem byte offsets
#define AS_OFF  0u            // 2 bufs x 8KB (fp16 P tile 64x64)
#define BT_OFF  16384u        // 2 bufs x (hi 16KB + lo 16KB)
#define F2_OFF  81920u        // 2048 floats
#define DI_OFF  90112u        // 64 floats
#define SMEM_TOT (90112 + 512)

// phase A for tile tt: adj in registers; P (fp16) into bufA[tt&1]
__device__ __forceinline__ float phase_a(int tt, char* smemA, float f1v,
                                         int4 m0, int4 m1,
                                         const float* f2p, uint32_t aRel) {
    float4 fa = *reinterpret_cast<const float4*>(f2p);
    float4 fb = *reinterpret_cast<const float4*>(f2p + 4);
    float s0 = f1v + fa.x; s0 = s0 > 0.f ? s0 : 0.2f * s0;
    float s1 = f1v + fa.y; s1 = s1 > 0.f ? s1 : 0.2f * s1;
    float s2 = f1v + fa.z; s2 = s2 > 0.f ? s2 : 0.2f * s2;
    float s3 = f1v + fa.w; s3 = s3 > 0.f ? s3 : 0.2f * s3;
    float p0 = (m0.x > 0) ? __expf(s0 - SHIFT) : 0.0f;
    float p1 = (m0.y > 0) ? __expf(s1 - SHIFT) : 0.0f;
    float p2 = (m0.z > 0) ? __expf(s2 - SHIFT) : 0.0f;
    float p3 = (m0.w > 0) ? __expf(s3 - SHIFT) : 0.0f;
    float s4 = f1v + fb.x; s4 = s4 > 0.f ? s4 : 0.2f * s4;
    float s5 = f1v + fb.y; s5 = s5 > 0.f ? s5 : 0.2f * s5;
    float s6 = f1v + fb.z; s6 = s6 > 0.f ? s6 : 0.2f * s6;
    float s7 = f1v + fb.w; s7 = s7 > 0.f ? s7 : 0.2f * s7;
    float p4 = (m1.x > 0) ? __expf(s4 - SHIFT) : 0.0f;
    float p5 = (m1.y > 0) ? __expf(s5 - SHIFT) : 0.0f;
    float p6 = (m1.z > 0) ? __expf(s6 - SHIFT) : 0.0f;
    float p7 = (m1.w > 0) ? __expf(s7 - SHIFT) : 0.0f;
    uint32_t off = AS_OFF + (uint32_t)(tt & 1) * 8192u + aRel;
    *reinterpret_cast<uint4*>(smemA + off) =
        make_uint4(pkh(p0, p1), pkh(p2, p3), pkh(p4, p5), pkh(p6, p7));
    return ((p0 + p1) + (p2 + p3)) + ((p4 + p5) + (p6 + p7));
}

__global__ void __launch_bounds__(512, 1)
k_attn(const int* __restrict__ adj, float* __restrict__ out) {
    extern __shared__ char smemA[];
    uint32_t sb = smem_u32(smemA);
    int tid = threadIdx.x;
    int wid = tid >> 5;
    int lane = tid & 31;
    int b = blockIdx.y;
    int row0 = blockIdx.x * RT;

    float* f2s = reinterpret_cast<float*>(smemA + F2_OFF);
    float* di = reinterpret_cast<float*>(smemA + DI_OFF);

    // ---- preload f2 row (8KB) ----
    {
        const float4* s4 = reinterpret_cast<const float4*>(g_f2 + b * NN);
        reinterpret_cast<float4*>(f2s)[tid] = s4[tid];
    }

    // ---- per-thread phase-A constants ----
    int r = tid >> 3;                 // 0..63
    int c8 = (tid & 7) * 8;           // j offset within tile
    float f1v = g_f1[b * NN + row0 + r];
    uint32_t aRel = swz((uint32_t)(r * 128 + (tid & 7) * 16));
    const int* adjp = adj + (size_t)(row0 + r) * NN + c8;

    // ---- MMA fragment addresses (warp tile 32 rows x 16 cols) ----
    int wr = wid >> 3, wc = wid & 7;
    uint32_t aOff0 = (uint32_t)((wr * 32 + (lane & 7) + ((lane >> 3) & 1) * 8) * 128
                                 + ((lane >> 4) & 1) * 16);
    uint32_t aOff1 = aOff0 + 16u * 128u;
    int bRow = wc * 16 + ((lane >> 4) & 1) * 8 + (lane & 7);
    uint32_t bBase = (uint32_t)(bRow * 128) + (uint32_t)(((lane >> 3) & 1) * 16);

    // cp.async B mapping (4 x 16B per thread per tile: hi + lo planes)
    uint32_t cpDst[4];
    const __half* cpSrcBase[4];
    #pragma unroll
    for (int k = 0; k < 4; k++) {
        int s = tid + k * 512;
        int split = s >> 10, s2 = s & 1023;
        int o = s2 >> 3, seg = s2 & 7;
        cpDst[k] = (uint32_t)split * 16384u + swz((uint32_t)(o * 128 + seg * 16));
        cpSrcBase[k] = (split ? g_WhT_l : g_WhT_h) + ((size_t)(b * 128 + o) * NN + seg * 8);
    }

    float acch[2][2][4] = {};
    float accl[2][2][4] = {};
    float dacc = 0.0f;

    // prologue: B(0); f2 visible; phase A(0) with direct adj load
    {
        uint32_t dbase = sb + BT_OFF;
        #pragma unroll
        for (int k = 0; k < 4; k++) CPA(dbase + cpDst[k], cpSrcBase[k]);
        CPC();
    }
    __syncthreads();
    {
        int4 m0 = *reinterpret_cast<const int4*>(adjp);
        int4 m1 = *reinterpret_cast<const int4*>(adjp + 4);
        dacc += phase_a(0, smemA, f1v, m0, m1, f2s + c8, aRel);
    }

    for (int t = 0; t < NTILE; t++) {
        uint32_t bufB = sb + BT_OFF + (uint32_t)(t & 1) * 32768u;
        uint32_t bufA = sb + AS_OFF + (uint32_t)(t & 1) * 8192u;

        __syncthreads();   // phaseA(t) + MMA(t-1) complete everywhere

        int4 nm0, nm1;
        if (t + 1 < NTILE) {
            uint32_t dbase = sb + BT_OFF + (uint32_t)((t + 1) & 1) * 32768u;
            #pragma unroll
            for (int k = 0; k < 4; k++) CPA(dbase + cpDst[k], cpSrcBase[k] + (t + 1) * KT);
            CPC();
            nm0 = *reinterpret_cast<const int4*>(adjp + (t + 1) * KT);      // hidden under MMA
            nm1 = *reinterpret_cast<const int4*>(adjp + (t + 1) * KT + 4);
            CPW(1);        // B(t) landed
        } else {
            CPW(0);
        }

        // ---- MMA(t): 4 ksteps x (2 m-frags x 2 n-frags x 2 terms) ----
        #pragma unroll
        for (int ks = 0; ks < 4; ks++) {
            uint32_t a0[4], a1[4], bh[4], bl[4];
            ldm4(a0, bufA + swz(aOff0 + 32u * ks));
            ldm4(a1, bufA + swz(aOff1 + 32u * ks));
            uint32_t bAddr = swz(bBase + 32u * ks);
            ldm4(bh, bufB + bAddr);
            ldm4(bl, bufB + 16384u + bAddr);
            mma16816(acch[0][0], a0, bh + 0);
            mma16816(acch[0][1], a0, bh + 2);
            mma16816(acch[1][0], a1, bh + 0);
            mma16816(acch[1][1], a1, bh + 2);
            mma16816(accl[0][0], a0, bl + 0);
            mma16816(accl[0][1], a0, bl + 2);
            mma16816(accl[1][0], a1, bl + 0);
            mma16816(accl[1][1], a1, bl + 2);
        }

        if (t + 1 < NTILE)
            dacc += phase_a(t + 1, smemA, f1v, nm0, nm1, f2s + (t + 1) * KT + c8, aRel);
    }

    // ---- softmax denominator (8 threads per row) ----
    dacc += __shfl_xor_sync(0xffffffffu, dacc, 1);
    dacc += __shfl_xor_sync(0xffffffffu, dacc, 2);
    dacc += __shfl_xor_sync(0xffffffffu, dacc, 4);
    if ((lane & 7) == 0) di[r] = 1.0f / dacc;
    __syncthreads();

    // ---- epilogue: merge terms, scale, store ----
    int rA = wr * 32 + (lane >> 2);
    #pragma unroll
    for (int mi = 0; mi < 2; mi++) {
        float dA = di[rA + mi * 16];
        float dB = di[rA + mi * 16 + 8];
        float* p0 = out + ((size_t)(b * NN + row0 + rA + mi * 16)) * NF
                        + wc * 16 + 2 * (lane & 3);
        float* p1 = p0 + 8 * NF;
        #pragma unroll
        for (int ni = 0; ni < 2; ni++) {
            *reinterpret_cast<float2*>(p0 + ni * 8) =
                make_float2((acch[mi][ni][0] + accl[mi][ni][0]) * dA,
                            (acch[mi][ni][1] + accl[mi][ni][1]) * dA);
            *reinterpret_cast<float2*>(p1 + ni * 8) =
                make_float2((acch[mi][ni][2] + accl[mi][ni][2]) * dB,
                            (acch[mi][ni][3] + accl[mi][ni][3]) * dB);
        }
    }
}

// ---------------------------------------------------------------------------
extern "C" void kernel_launch(void* const* d_in, const int* in_sizes, int n_in,
                              void* d_out, int out_size) {
    const float* h   = (const float*)d_in[0];
    const int*   adj = (const int*)d_in[1];
    const float* W   = (const float*)d_in[2];
    const float* a   = (const float*)d_in[3];
    float* out = (float*)d_out;

    int sm1 = (32 * 128 + 128 * 128) * 4;
    cudaFuncSetAttribute(k_gemm1, cudaFuncAttributeMaxDynamicSharedMemorySize, sm1);
    cudaFuncSetAttribute(k_attn,  cudaFuncAttributeMaxDynamicSharedMemorySize, SMEM_TOT);

    k_gemm1<<<(NB * NN) / 32, 256, sm1>>>(h, W, a);
    k_attn<<<dim3(NN / RT, NB), 512, SMEM_TOT>>>(adj, out);
}

// round 11
// speedup vs baseline: 1.5205x; 1.2276x over previous
#include <cuda_runtime.h>
#include <cuda_fp16.h>
#include <cstdint>

#define NB 4
#define NN 2048
#define NF 128
#define RT 64        // rows per attention block (M)
#define KT 64        // j per K tile
#define NTILE (NN / KT)
#define SHIFT 4.0f

// ---- scratch (no cudaMalloc allowed) ----
__device__ __half g_WhT_h[NB * NF * NN];   // [b][o][n] fp16
__device__ float  g_f1[NB * NN];
__device__ float  g_f2[NB * NN];

// ---------------------------------------------------------------------------
__device__ __forceinline__ uint32_t smem_u32(const void* p) {
    uint32_t a;
    asm("{ .reg .u64 t; cvta.to.shared.u64 t, %1; cvt.u32.u64 %0, t; }" : "=r"(a) : "l"(p));
    return a;
}
__device__ __forceinline__ uint32_t swz(uint32_t x) { return x ^ ((x >> 3) & 0x70); }

__device__ __forceinline__ uint32_t pkh(float a, float b) {   // fp16x2: lo<-a, hi<-b
    uint32_t r;
    asm("cvt.rn.f16x2.f32 %0, %1, %2;" : "=r"(r) : "f"(b), "f"(a));
    return r;
}
__device__ __forceinline__ void ldm4(uint32_t* r, uint32_t addr) {
    asm volatile("ldmatrix.sync.aligned.m8n8.x4.shared.b16 {%0,%1,%2,%3}, [%4];"
        : "=r"(r[0]), "=r"(r[1]), "=r"(r[2]), "=r"(r[3]) : "r"(addr));
}
__device__ __forceinline__ void mma16816(float* d, const uint32_t* a, const uint32_t* b) {
    asm volatile("mma.sync.aligned.m16n8k16.row.col.f32.f16.f16.f32 "
        "{%0,%1,%2,%3}, {%4,%5,%6,%7}, {%8,%9}, {%0,%1,%2,%3};"
        : "+f"(d[0]), "+f"(d[1]), "+f"(d[2]), "+f"(d[3])
        : "r"(a[0]), "r"(a[1]), "r"(a[2]), "r"(a[3]), "r"(b[0]), "r"(b[1]));
}
#define CPA(dst, src) asm volatile("cp.async.cg.shared.global [%0], [%1], 16;" :: "r"(dst), "l"(src) : "memory")
#define CPC()   asm volatile("cp.async.commit_group;" ::: "memory")
#define CPW(n)  asm volatile("cp.async.wait_group %0;" :: "n"(n) : "memory")

// ---------------------------------------------------------------------------
// Kernel 1: Wh = h@W (fp32) ; f1/f2 ; WhT (fp16 hi only, coalesced stores)
// ---------------------------------------------------------------------------
__global__ void k_gemm1(const float* __restrict__ h,
                        const float* __restrict__ W,
                        const float* __restrict__ a) {
    extern __shared__ float sm1[];
    float* hs = sm1;
    float* Ws = sm1 + 32 * 128;
    int tid = threadIdx.x;
    int m0 = blockIdx.x * 32;

    {
        const float4* src = reinterpret_cast<const float4*>(h + (size_t)m0 * NF);
        float4* dst = reinterpret_cast<float4*>(hs);
        #pragma unroll
        for (int it = 0; it < 4; it++) dst[tid + it * 256] = src[tid + it * 256];
    }
    {
        const float4* src = reinterpret_cast<const float4*>(W);
        float4* dst = reinterpret_cast<float4*>(Ws);
        #pragma unroll
        for (int it = 0; it < 16; it++) dst[tid + it * 256] = src[tid + it * 256];
    }
    __syncthreads();

    int ty = tid >> 5;
    int tx = tid & 31;
    float acc[4][4] = {};

    #pragma unroll 4
    for (int k = 0; k < 128; k++) {
        float4 bv = *reinterpret_cast<const float4*>(&Ws[k * 128 + tx * 4]);
        #pragma unroll
        for (int mi = 0; mi < 4; mi++) {
            float av = hs[(ty * 4 + mi) * 128 + k];
            acc[mi][0] += av * bv.x;
            acc[mi][1] += av * bv.y;
            acc[mi][2] += av * bv.z;
            acc[mi][3] += av * bv.w;
        }
    }

    float a1v[4], a2v[4];
    #pragma unroll
    for (int ni = 0; ni < 4; ni++) {
        a1v[ni] = a[tx * 4 + ni];
        a2v[ni] = a[NF + tx * 4 + ni];
    }
    #pragma unroll
    for (int mi = 0; mi < 4; mi++) {
        float p1 = acc[mi][0] * a1v[0] + acc[mi][1] * a1v[1]
                 + acc[mi][2] * a1v[2] + acc[mi][3] * a1v[3];
        float p2 = acc[mi][0] * a2v[0] + acc[mi][1] * a2v[1]
                 + acc[mi][2] * a2v[2] + acc[mi][3] * a2v[3];
        #pragma unroll
        for (int off = 16; off > 0; off >>= 1) {
            p1 += __shfl_xor_sync(0xffffffffu, p1, off);
            p2 += __shfl_xor_sync(0xffffffffu, p2, off);
        }
        if (tx == 0) {
            g_f1[m0 + ty * 4 + mi] = p1;
            g_f2[m0 + ty * 4 + mi] = p2;
        }
    }

    // ---- transposed fp16 store via smem (coalesced) ----
    __syncthreads();                 // hs/Ws no longer needed
    uint32_t* su = reinterpret_cast<uint32_t*>(sm1);            // [128 o][16+1 pad]
    #pragma unroll
    for (int ni = 0; ni < 4; ni++) {
        int o = tx * 4 + ni;
        su[o * 17 + ty * 2]     = pkh(acc[0][ni], acc[1][ni]);
        su[o * 17 + ty * 2 + 1] = pkh(acc[2][ni], acc[3][ni]);
    }
    __syncthreads();
    int bb = m0 >> 11;
    int o = tid >> 1, half = tid & 1;
    uint32_t* dh = reinterpret_cast<uint32_t*>(g_WhT_h)
                   + (size_t)(bb * 128 + o) * 1024 + ((m0 & 2047) >> 1) + half * 8;
    const uint32_t* sh = su + o * 17 + half * 8;
    uint4 t0 = make_uint4(sh[0], sh[1], sh[2], sh[3]);
    uint4 t1 = make_uint4(sh[4], sh[5], sh[6], sh[7]);
    *reinterpret_cast<uint4*>(dh)     = t0;
    *reinterpret_cast<uint4*>(dh + 4) = t1;
}

// ---------------------------------------------------------------------------
// Kernel 2: fused attention, 1024 threads, warp tile 16x16, single B plane,
// adj via LDG->registers.
// ---------------------------------------------------------------------------
// smem byte offsets
#define AS_OFF  0u            // 2 bufs x 8KB (fp16 P tile 64x64)
#define BT_OFF  16384u        // 2 bufs x 16KB
#define F2_OFF  49152u        // 2048 floats
#define DI_OFF  57344u        // 64 floats
#define SMEM_TOT (57344 + 512)

// phase A for tile tt: adj in registers; P (fp16, 4 j/thread) into bufA[tt&1]
__device__ __forceinline__ float phase_a(int tt, char* smemA, float f1v, int4 m0,
                                         const float* f2p, uint32_t aRel) {
    float4 fa = *reinterpret_cast<const float4*>(f2p);
    float s0 = f1v + fa.x; s0 = s0 > 0.f ? s0 : 0.2f * s0;
    float s1 = f1v + fa.y; s1 = s1 > 0.f ? s1 : 0.2f * s1;
    float s2 = f1v + fa.z; s2 = s2 > 0.f ? s2 : 0.2f * s2;
    float s3 = f1v + fa.w; s3 = s3 > 0.f ? s3 : 0.2f * s3;
    float p0 = (m0.x > 0) ? __expf(s0 - SHIFT) : 0.0f;
    float p1 = (m0.y > 0) ? __expf(s1 - SHIFT) : 0.0f;
    float p2 = (m0.z > 0) ? __expf(s2 - SHIFT) : 0.0f;
    float p3 = (m0.w > 0) ? __expf(s3 - SHIFT) : 0.0f;
    uint32_t off = AS_OFF + (uint32_t)(tt & 1) * 8192u + aRel;
    *reinterpret_cast<uint2*>(smemA + off) = make_uint2(pkh(p0, p1), pkh(p2, p3));
    return (p0 + p1) + (p2 + p3);
}

__global__ void __launch_bounds__(1024, 1)
k_attn(const int* __restrict__ adj, float* __restrict__ out) {
    extern __shared__ char smemA[];
    uint32_t sb = smem_u32(smemA);
    int tid = threadIdx.x;
    int wid = tid >> 5;
    int lane = tid & 31;
    int b = blockIdx.y;
    int row0 = blockIdx.x * RT;

    float* f2s = reinterpret_cast<float*>(smemA + F2_OFF);
    float* di = reinterpret_cast<float*>(smemA + DI_OFF);

    // ---- preload f2 row (8KB) ----
    {
        const float2* s2 = reinterpret_cast<const float2*>(g_f2 + b * NN);
        reinterpret_cast<float2*>(f2s)[tid] = s2[tid];
    }

    // ---- per-thread phase-A constants ----
    int r = tid >> 4;                 // 0..63
    int c4 = (tid & 15) * 4;          // j offset within tile
    float f1v = g_f1[b * NN + row0 + r];
    uint32_t aRel = swz((uint32_t)(r * 128 + (tid & 15) * 8));
    const int* adjp = adj + (size_t)(row0 + r) * NN + c4;

    // ---- MMA fragment addresses (warp: 16 rows x 16 cols) ----
    int wr = wid >> 3, wc = wid & 7;
    uint32_t aRowOff = (uint32_t)((wr * 16 + (lane & 7) + ((lane >> 3) & 1) * 8) * 128
                                  + ((lane >> 4) & 1) * 16);
    int bRow = wc * 16 + ((lane >> 4) & 1) * 8 + (lane & 7);
    uint32_t bBase = (uint32_t)(bRow * 128) + (uint32_t)(((lane >> 3) & 1) * 16);

    // cp.async B mapping (1 x 16B per thread per tile)
    int oo = tid >> 3, seg = tid & 7;
    uint32_t cpDst = swz((uint32_t)(oo * 128 + seg * 16));
    const __half* cpSrcBase = g_WhT_h + ((size_t)(b * 128 + oo) * NN + seg * 8);

    float acc[2][4] = {};
    float dacc = 0.0f;

    // prologue: B(0); f2 visible; phase A(0) with direct adj load
    CPA(sb + BT_OFF + cpDst, cpSrcBase);
    CPC();
    __syncthreads();
    {
        int4 m0 = *reinterpret_cast<const int4*>(adjp);
        dacc += phase_a(0, smemA, f1v, m0, f2s + c4, aRel);
    }

    for (int t = 0; t < NTILE; t++) {
        uint32_t bufB = sb + BT_OFF + (uint32_t)(t & 1) * 16384u;
        uint32_t bufA = sb + AS_OFF + (uint32_t)(t & 1) * 8192u;

        __syncthreads();   // phaseA(t) + MMA(t-1) complete everywhere

        int4 nm0;
        if (t + 1 < NTILE) {
            uint32_t dbase = sb + BT_OFF + (uint32_t)((t + 1) & 1) * 16384u;
            CPA(dbase + cpDst, cpSrcBase + (t + 1) * KT);
            CPC();
            nm0 = *reinterpret_cast<const int4*>(adjp + (t + 1) * KT);   // hidden under MMA
            CPW(1);        // B(t) landed
        } else {
            CPW(0);
        }

        // ---- MMA(t): 4 ksteps x 2 nfrags ----
        #pragma unroll
        for (int ks = 0; ks < 4; ks++) {
            uint32_t ah[4], bh[4];
            ldm4(ah, bufA + swz(aRowOff + 32u * ks));
            ldm4(bh, bufB + swz(bBase + 32u * ks));
            mma16816(acc[0], ah, bh + 0);
            mma16816(acc[1], ah, bh + 2);
        }

        if (t + 1 < NTILE)
            dacc += phase_a(t + 1, smemA, f1v, nm0, f2s + (t + 1) * KT + c4, aRel);
    }

    // ---- softmax denominator (16 threads per row) ----
    dacc += __shfl_xor_sync(0xffffffffu, dacc, 1);
    dacc += __shfl_xor_sync(0xffffffffu, dacc, 2);
    dacc += __shfl_xor_sync(0xffffffffu, dacc, 4);
    dacc += __shfl_xor_sync(0xffffffffu, dacc, 8);
    if ((lane & 15) == 0) di[r] = 1.0f / dacc;
    __syncthreads();

    // ---- epilogue: scale + store ----
    int rA = wr * 16 + (lane >> 2);
    float d0 = di[rA];
    float d1 = di[rA + 8];
    float* orow0 = out + ((size_t)(b * NN + row0 + rA)) * NF + wc * 16 + 2 * (lane & 3);
    float* orow1 = orow0 + 8 * NF;
    #pragma unroll
    for (int nb = 0; nb < 2; nb++) {
        *reinterpret_cast<float2*>(orow0 + nb * 8) =
            make_float2(acc[nb][0] * d0, acc[nb][1] * d0);
        *reinterpret_cast<float2*>(orow1 + nb * 8) =
            make_float2(acc[nb][2] * d1, acc[nb][3] * d1);
    }
}

// ---------------------------------------------------------------------------
extern "C" void kernel_launch(void* const* d_in, const int* in_sizes, int n_in,
                              void* d_out, int out_size) {
    const float* h   = (const float*)d_in[0];
    const int*   adj = (const int*)d_in[1];
    const float* W   = (const float*)d_in[2];
    const float* a   = (const float*)d_in[3];
    float* out = (float*)d_out;

    int sm1 = (32 * 128 + 128 * 128) * 4;
    cudaFuncSetAttribute(k_gemm1, cudaFuncAttributeMaxDynamicSharedMemorySize, sm1);
    cudaFuncSetAttribute(k_attn,  cudaFuncAttributeMaxDynamicSharedMemorySize, SMEM_TOT);

    k_gemm1<<<(NB * NN) / 32, 256, sm1>>>(h, W, a);
    k_attn<<<dim3(NN / RT, NB), 1024, SMEM_TOT>>>(adj, out);
}